// round 1
// baseline (speedup 1.0000x reference)
#include <cuda_runtime.h>
#include <math.h>

#define TT   2048
#define CC   512
#define HH   8
#define DHD  64
#define WINW 48
#define NW   97      // 2*WIN+1
#define C3   1536

// Scratch (device globals — no allocation allowed)
__device__ float g_qkv[TT * C3];   // 12 MB
__device__ float g_y[TT * CC];     // 4 MB

// ---------------------------------------------------------------------------
// Tiled fp32 GEMM: C[M,N] = A[M,K] @ B[K,N], all row-major.
// 64x64 tile, 256 threads, 4x4 micro-tile per thread, K-step 16.
// Requires M%64==0, N%64==0, K%16==0 (true for both GEMMs here).
// ---------------------------------------------------------------------------
template<int M, int N, int K>
__global__ void gemm_kernel(const float* __restrict__ A,
                            const float* __restrict__ B,
                            float* __restrict__ Cout) {
    __shared__ float As[16][68];   // [k][m], row stride 68 floats = 272B (16B aligned)
    __shared__ float Bs[16][64];   // [k][n]

    const int t  = threadIdx.x;            // 0..255
    const int n0 = blockIdx.x * 64;
    const int m0 = blockIdx.y * 64;
    const int tx = t & 15;                 // n sub-tile
    const int ty = t >> 4;                 // m sub-tile

    float acc[4][4];
#pragma unroll
    for (int i = 0; i < 4; i++)
#pragma unroll
        for (int j = 0; j < 4; j++) acc[i][j] = 0.f;

    for (int k0 = 0; k0 < K; k0 += 16) {
        // Load A tile: 64 rows x 16 k  (one float4 per thread, transposed store)
        {
            const int row = t >> 2;
            const int kk  = (t & 3) * 4;
            const float4 a = *(const float4*)&A[(size_t)(m0 + row) * K + k0 + kk];
            As[kk + 0][row] = a.x;
            As[kk + 1][row] = a.y;
            As[kk + 2][row] = a.z;
            As[kk + 3][row] = a.w;
        }
        // Load B tile: 16 k x 64 cols (one float4 per thread)
        {
            const int kk = t >> 4;
            const int j  = (t & 15) * 4;
            *(float4*)&Bs[kk][j] = *(const float4*)&B[(size_t)(k0 + kk) * N + n0 + j];
        }
        __syncthreads();

#pragma unroll
        for (int kk = 0; kk < 16; kk++) {
            float a[4], b[4];
#pragma unroll
            for (int i = 0; i < 4; i++) a[i] = As[kk][ty * 4 + i];
#pragma unroll
            for (int j = 0; j < 4; j++) b[j] = Bs[kk][tx * 4 + j];
#pragma unroll
            for (int i = 0; i < 4; i++)
#pragma unroll
                for (int j = 0; j < 4; j++) acc[i][j] = fmaf(a[i], b[j], acc[i][j]);
        }
        __syncthreads();
    }

#pragma unroll
    for (int i = 0; i < 4; i++) {
        float4 v = make_float4(acc[i][0], acc[i][1], acc[i][2], acc[i][3]);
        *(float4*)&Cout[(size_t)(m0 + ty * 4 + i) * N + n0 + tx * 4] = v;
    }
}

// ---------------------------------------------------------------------------
// Permuted sliding-window attention. One warp per (head, permuted position t).
// Lanes split DH=64 into float2 each. Scores via butterfly reduce; per-lane
// softmax state for owned offsets; weights shuffled back for the PV pass.
// ---------------------------------------------------------------------------
__global__ void attn_kernel(const float* __restrict__ qkv,
                            const int* __restrict__ perms,
                            float* __restrict__ y) {
    const int h    = blockIdx.y;
    const int t    = blockIdx.x * 8 + (threadIdx.x >> 5);
    const int lane = threadIdx.x & 31;

    const int* __restrict__ perm = perms + h * TT;
    const int pt = perm[t];

    const float* __restrict__ qrow = qkv + (size_t)pt * C3 + h * DHD;
    const float2 q = *(const float2*)(qrow + 2 * lane);

    float s[4];
    int   pj_own[4];
#pragma unroll
    for (int i = 0; i < 4; i++) { s[i] = -INFINITY; pj_own[i] = 0; }
    float smax = -INFINITY;

    const float* __restrict__ kbase = qkv + CC + h * DHD + 2 * lane;

#pragma unroll
    for (int o = 0; o < NW; o++) {
        const int j = t + o - WINW;
        float sc = -INFINITY;
        int pj = 0;
        if (j >= 0 && j < TT) {
            pj = perm[j];                     // uniform broadcast load
            if (pj <= pt) {                   // uniform predicate
                const float2 kv = *(const float2*)(kbase + (size_t)pj * C3);
                float d = q.x * kv.x + q.y * kv.y;
#pragma unroll
                for (int off = 16; off; off >>= 1)
                    d += __shfl_xor_sync(0xffffffffu, d, off);
                sc = d * 0.125f;              // 1/sqrt(64)
            }
        }
        if ((o & 31) == lane) { s[o >> 5] = sc; pj_own[o >> 5] = pj; }
        smax = fmaxf(smax, sc);               // sc uniform across lanes
    }

    // Softmax (unnormalized weights; divide at the end)
    float w[4];
    float denom = 0.f;
#pragma unroll
    for (int i = 0; i < 4; i++) {
        w[i] = __expf(s[i] - smax);           // -inf -> 0
        denom += w[i];
    }
#pragma unroll
    for (int off = 16; off; off >>= 1)
        denom += __shfl_xor_sync(0xffffffffu, denom, off);

    const float* __restrict__ vbase = qkv + 2 * CC + h * DHD + 2 * lane;
    float a0 = 0.f, a1 = 0.f;
#pragma unroll
    for (int o = 0; o < NW; o++) {
        const float wo = __shfl_sync(0xffffffffu, w[o >> 5], o & 31);
        const int  pj  = __shfl_sync(0xffffffffu, pj_own[o >> 5], o & 31);
        if (wo > 0.f) {                       // uniform
            const float2 vv = *(const float2*)(vbase + (size_t)pj * C3);
            a0 = fmaf(wo, vv.x, a0);
            a1 = fmaf(wo, vv.y, a1);
        }
    }
    const float inv = 1.f / denom;
    float2 out; out.x = a0 * inv; out.y = a1 * inv;
    *(float2*)(y + (size_t)pt * CC + h * DHD + 2 * lane) = out;
}

// ---------------------------------------------------------------------------
extern "C" void kernel_launch(void* const* d_in, const int* in_sizes, int n_in,
                              void* d_out, int out_size) {
    (void)in_sizes; (void)n_in; (void)out_size;
    const float* x     = (const float*)d_in[0];   // [2048, 512]
    const float* Wqkv  = (const float*)d_in[1];   // [512, 1536]
    const float* Wout  = (const float*)d_in[2];   // [512, 512]
    const int*   perms = (const int*)d_in[3];     // [8, 2048]
    float*       out   = (float*)d_out;           // [2048, 512]

    float* qkv = nullptr;
    float* y   = nullptr;
    cudaGetSymbolAddress((void**)&qkv, g_qkv);
    cudaGetSymbolAddress((void**)&y,   g_y);

    // 1) qkv = x @ W_qkv
    gemm_kernel<TT, C3, CC><<<dim3(C3 / 64, TT / 64), 256>>>(x, Wqkv, qkv);
    // 2) permuted windowed attention -> y (scatter through perm)
    attn_kernel<<<dim3(TT / 8, HH), 256>>>(qkv, perms, y);
    // 3) out = y @ W_out
    gemm_kernel<TT, CC, CC><<<dim3(CC / 64, TT / 64), 256>>>(y, Wout, out);
}

// round 2
// speedup vs baseline: 1.8383x; 1.8383x over previous
#include <cuda_runtime.h>
#include <math.h>
#include <stdint.h>

#define TT   2048
#define CC   512
#define HH   8
#define DHD  64
#define WINW 48
#define C3   1536
#define QB   32          // queries per attention block
#define BAND 128         // QB + 2*WIN = 32 + 96

// Scratch (device globals — no allocation allowed)
__device__ float g_qkv[TT * C3];   // 12 MB
__device__ float g_y[TT * CC];     // 4 MB

// ---------------------------------------------------------------------------
// TF32 helpers
// ---------------------------------------------------------------------------
__device__ __forceinline__ float to_tf32(float x) {
    float y;
    asm("cvt.rna.tf32.f32 %0, %1;" : "=f"(y) : "f"(x));
    return y;
}

__device__ __forceinline__ void mma_tf32(float& c0, float& c1, float& c2, float& c3,
                                         uint32_t a0, uint32_t a1, uint32_t a2, uint32_t a3,
                                         uint32_t b0, uint32_t b1) {
    asm volatile(
        "mma.sync.aligned.m16n8k8.row.col.f32.tf32.tf32.f32 "
        "{%0,%1,%2,%3}, {%4,%5,%6,%7}, {%8,%9}, {%0,%1,%2,%3};"
        : "+f"(c0), "+f"(c1), "+f"(c2), "+f"(c3)
        : "r"(a0), "r"(a1), "r"(a2), "r"(a3), "r"(b0), "r"(b1));
}

// ---------------------------------------------------------------------------
// TF32 tensor-core GEMM: C[M,N] = A[M,K] @ B[K,N], row-major.
// Block tile 128x64, 8 warps (4m x 2n), warp tile 32x32 (2x4 mma of m16n8k8).
// Requires M%128==0, N%64==0, K%16==0.
// ---------------------------------------------------------------------------
template<int M, int N, int K>
__global__ void __launch_bounds__(256) gemm_tf32_kernel(
    const float* __restrict__ A,
    const float* __restrict__ B,
    float* __restrict__ Cout)
{
    __shared__ float As[128][17];   // [m][k], pad to 17
    __shared__ float Bs[16][68];    // [k][n], pad to 68

    const int t    = threadIdx.x;
    const int lane = t & 31;
    const int w    = t >> 5;
    const int wm   = (w >> 1) * 32;   // warp m-offset within block
    const int wn   = (w & 1) * 32;    // warp n-offset within block
    const int m0   = blockIdx.y * 128;
    const int n0   = blockIdx.x * 64;

    const int lq = lane >> 2;   // lane/4
    const int lr = lane & 3;    // lane%4

    float c[2][4][4];
#pragma unroll
    for (int mt = 0; mt < 2; mt++)
#pragma unroll
        for (int nt = 0; nt < 4; nt++)
#pragma unroll
            for (int i = 0; i < 4; i++) c[mt][nt][i] = 0.f;

    for (int k0 = 0; k0 < K; k0 += 16) {
        // Load A tile 128x16: thread -> row t>>1, k-chunk (t&1)*8 (two float4)
        {
            const int row = t >> 1;
            const int kk  = (t & 1) * 8;
            const float4 v0 = *(const float4*)&A[(size_t)(m0 + row) * K + k0 + kk];
            const float4 v1 = *(const float4*)&A[(size_t)(m0 + row) * K + k0 + kk + 4];
            As[row][kk + 0] = to_tf32(v0.x);
            As[row][kk + 1] = to_tf32(v0.y);
            As[row][kk + 2] = to_tf32(v0.z);
            As[row][kk + 3] = to_tf32(v0.w);
            As[row][kk + 4] = to_tf32(v1.x);
            As[row][kk + 5] = to_tf32(v1.y);
            As[row][kk + 6] = to_tf32(v1.z);
            As[row][kk + 7] = to_tf32(v1.w);
        }
        // Load B tile 16x64: thread -> row t>>4, col (t&15)*4
        {
            const int row = t >> 4;
            const int col = (t & 15) * 4;
            const float4 v = *(const float4*)&B[(size_t)(k0 + row) * N + n0 + col];
            float4 o;
            o.x = to_tf32(v.x); o.y = to_tf32(v.y);
            o.z = to_tf32(v.z); o.w = to_tf32(v.w);
            *(float4*)&Bs[row][col] = o;
        }
        __syncthreads();

#pragma unroll
        for (int kk8 = 0; kk8 < 16; kk8 += 8) {
            uint32_t af[2][4];
#pragma unroll
            for (int mt = 0; mt < 2; mt++) {
                const int mb = wm + mt * 16;
                af[mt][0] = __float_as_uint(As[mb + lq    ][kk8 + lr    ]);
                af[mt][1] = __float_as_uint(As[mb + lq + 8][kk8 + lr    ]);
                af[mt][2] = __float_as_uint(As[mb + lq    ][kk8 + lr + 4]);
                af[mt][3] = __float_as_uint(As[mb + lq + 8][kk8 + lr + 4]);
            }
            uint32_t bf[4][2];
#pragma unroll
            for (int nt = 0; nt < 4; nt++) {
                const int col = wn + nt * 8 + lq;
                bf[nt][0] = __float_as_uint(Bs[kk8 + lr    ][col]);
                bf[nt][1] = __float_as_uint(Bs[kk8 + lr + 4][col]);
            }
#pragma unroll
            for (int mt = 0; mt < 2; mt++)
#pragma unroll
                for (int nt = 0; nt < 4; nt++)
                    mma_tf32(c[mt][nt][0], c[mt][nt][1], c[mt][nt][2], c[mt][nt][3],
                             af[mt][0], af[mt][1], af[mt][2], af[mt][3],
                             bf[nt][0], bf[nt][1]);
        }
        __syncthreads();
    }

    // Epilogue
#pragma unroll
    for (int mt = 0; mt < 2; mt++) {
#pragma unroll
        for (int nt = 0; nt < 4; nt++) {
            const int row0 = m0 + wm + mt * 16 + lq;
            const int col  = n0 + wn + nt * 8 + 2 * lr;
            *(float2*)&Cout[(size_t)row0 * N + col] =
                make_float2(c[mt][nt][0], c[mt][nt][1]);
            *(float2*)&Cout[(size_t)(row0 + 8) * N + col] =
                make_float2(c[mt][nt][2], c[mt][nt][3]);
        }
    }
}

// ---------------------------------------------------------------------------
// Attention v2: block = (head, 32 consecutive permuted queries).
// Stage Q (transposed), K band (transposed), V band in smem; compute
// S = Q K^T as dense 32x128 GEMM, masked softmax, then Y = W V.
// ---------------------------------------------------------------------------
#define QS_STRIDE  36   // Qs[d][q]  : 64 x 36
#define KS_STRIDE  132  // Ks[d][r]  : 64 x 132
#define VS_STRIDE  68   // Vs[r][d]  : 128 x 68
#define WT_STRIDE  33   // Wt[r][q]  : 128 x 33

#define QS_OFF   0
#define KS_OFF   (QS_OFF + 64 * QS_STRIDE)                // 2304
#define VS_OFF   (KS_OFF + 64 * KS_STRIDE)                // 10752
#define WT_OFF   (VS_OFF + BAND * VS_STRIDE)              // 19456
#define NB_OFF   (WT_OFF + BAND * WT_STRIDE)              // 23680 (ints)
#define PT_OFF   (NB_OFF + BAND)
#define ATTN_SMEM_FLOATS (PT_OFF + QB)
#define ATTN_SMEM_BYTES  (ATTN_SMEM_FLOATS * 4)

__global__ void __launch_bounds__(256) attn2_kernel(
    const float* __restrict__ qkv,
    const int* __restrict__ perms,
    float* __restrict__ y)
{
    extern __shared__ float sm[];
    float* Qs = sm + QS_OFF;
    float* Ks = sm + KS_OFF;
    float* Vs = sm + VS_OFF;
    float* Wt = sm + WT_OFF;
    int*   nb = (int*)(sm + NB_OFF);
    int*   pts = (int*)(sm + PT_OFF);

    const int h    = blockIdx.y;
    const int t0   = blockIdx.x * QB;
    const int t    = threadIdx.x;
    const int lane = t & 31;
    const int w    = t >> 5;

    const int* __restrict__ perm = perms + h * TT;

    // --- index staging ---
    for (int i = t; i < BAND + QB; i += 256) {
        if (i < BAND) {
            int j  = t0 - WINW + i;
            int jc = min(max(j, 0), TT - 1);
            nb[i] = perm[jc];
        } else {
            pts[i - BAND] = perm[t0 + (i - BAND)];
        }
    }
    __syncthreads();

    // --- fill tiles (warp per row, lane = 2 consecutive d) ---
    // K band, transposed: Ks[d][r]
    for (int it = 0; it < BAND / 8; it++) {
        const int r = it * 8 + w;
        const float2 kv = *(const float2*)&qkv[(size_t)nb[r] * C3 + CC + h * DHD + 2 * lane];
        Ks[(2 * lane    ) * KS_STRIDE + r] = kv.x;
        Ks[(2 * lane + 1) * KS_STRIDE + r] = kv.y;
        // V band, natural: Vs[r][d]
        const float2 vv = *(const float2*)&qkv[(size_t)nb[r] * C3 + 2 * CC + h * DHD + 2 * lane];
        *(float2*)&Vs[r * VS_STRIDE + 2 * lane] = vv;
    }
    // Q, transposed + scaled: Qs[d][q]
    for (int it = 0; it < QB / 8; it++) {
        const int q = it * 8 + w;
        const float2 qv = *(const float2*)&qkv[(size_t)pts[q] * C3 + h * DHD + 2 * lane];
        Qs[(2 * lane    ) * QS_STRIDE + q] = qv.x * 0.125f;
        Qs[(2 * lane + 1) * QS_STRIDE + q] = qv.y * 0.125f;
    }
    __syncthreads();

    // --- S = Q K^T : 32q x 128r, thread grid 8(q) x 32(r), micro 4x4 ---
    {
        const int tq = t >> 5;   // 0..7
        const int tr = t & 31;   // 0..31
        float acc[4][4];
#pragma unroll
        for (int i = 0; i < 4; i++)
#pragma unroll
            for (int j = 0; j < 4; j++) acc[i][j] = 0.f;

#pragma unroll 4
        for (int d = 0; d < DHD; d++) {
            const float4 qv = *(const float4*)&Qs[d * QS_STRIDE + tq * 4];
            const float4 kv = *(const float4*)&Ks[d * KS_STRIDE + tr * 4];
            const float qa[4] = {qv.x, qv.y, qv.z, qv.w};
            const float ka[4] = {kv.x, kv.y, kv.z, kv.w};
#pragma unroll
            for (int i = 0; i < 4; i++)
#pragma unroll
                for (int j = 0; j < 4; j++)
                    acc[i][j] = fmaf(qa[i], ka[j], acc[i][j]);
        }
#pragma unroll
        for (int i = 0; i < 4; i++)
#pragma unroll
            for (int j = 0; j < 4; j++)
                Wt[(tr * 4 + j) * WT_STRIDE + tq * 4 + i] = acc[i][j];
    }
    __syncthreads();

    // --- masked softmax: warp per query, lane strides the 128 band rows ---
    for (int qq = w; qq < QB; qq += 8) {
        const int pt = pts[qq];
        float v[4];
#pragma unroll
        for (int c = 0; c < 4; c++) {
            const int r = lane + 32 * c;
            const bool m = (r >= qq) && (r <= qq + 96) &&
                           ((unsigned)(t0 - WINW + r) < (unsigned)TT) &&
                           (nb[r] <= pt);
            v[c] = m ? Wt[r * WT_STRIDE + qq] : -INFINITY;
        }
        float mx = fmaxf(fmaxf(v[0], v[1]), fmaxf(v[2], v[3]));
#pragma unroll
        for (int off = 16; off; off >>= 1)
            mx = fmaxf(mx, __shfl_xor_sync(0xffffffffu, mx, off));
        float e[4], s = 0.f;
#pragma unroll
        for (int c = 0; c < 4; c++) { e[c] = __expf(v[c] - mx); s += e[c]; }
#pragma unroll
        for (int off = 16; off; off >>= 1)
            s += __shfl_xor_sync(0xffffffffu, s, off);
        const float inv = 1.f / s;
#pragma unroll
        for (int c = 0; c < 4; c++) {
            const int r = lane + 32 * c;
            Wt[r * WT_STRIDE + qq] = e[c] * inv;
        }
    }
    __syncthreads();

    // --- Y = W V : 32q x 64d, thread grid 8(q) x 32(d-pairs), micro 4x2 ---
    {
        const int tq = t >> 5;   // 0..7
        const int td = t & 31;   // 0..31 (2 d each)
        float a0[4], a1[4];
#pragma unroll
        for (int i = 0; i < 4; i++) { a0[i] = 0.f; a1[i] = 0.f; }

#pragma unroll 4
        for (int r = 0; r < BAND; r++) {
            const float2 vv = *(const float2*)&Vs[r * VS_STRIDE + td * 2];
            const float* wr = &Wt[r * WT_STRIDE + tq * 4];
#pragma unroll
            for (int i = 0; i < 4; i++) {
                const float wi = wr[i];
                a0[i] = fmaf(wi, vv.x, a0[i]);
                a1[i] = fmaf(wi, vv.y, a1[i]);
            }
        }
#pragma unroll
        for (int i = 0; i < 4; i++) {
            const int q  = tq * 4 + i;
            const int pt = pts[q];
            *(float2*)&y[(size_t)pt * CC + h * DHD + td * 2] = make_float2(a0[i], a1[i]);
        }
    }
}

// ---------------------------------------------------------------------------
extern "C" void kernel_launch(void* const* d_in, const int* in_sizes, int n_in,
                              void* d_out, int out_size) {
    (void)in_sizes; (void)n_in; (void)out_size;
    const float* x     = (const float*)d_in[0];   // [2048, 512]
    const float* Wqkv  = (const float*)d_in[1];   // [512, 1536]
    const float* Wout  = (const float*)d_in[2];   // [512, 512]
    const int*   perms = (const int*)d_in[3];     // [8, 2048]
    float*       out   = (float*)d_out;           // [2048, 512]

    float* qkv = nullptr;
    float* y   = nullptr;
    cudaGetSymbolAddress((void**)&qkv, g_qkv);
    cudaGetSymbolAddress((void**)&y,   g_y);

    static bool attr_set = false;
    if (!attr_set) {
        cudaFuncSetAttribute(attn2_kernel,
                             cudaFuncAttributeMaxDynamicSharedMemorySize,
                             ATTN_SMEM_BYTES);
        attr_set = true;
    }

    // 1) qkv = x @ W_qkv   (tf32 tensor cores)
    gemm_tf32_kernel<TT, C3, CC><<<dim3(C3 / 64, TT / 128), 256>>>(x, Wqkv, qkv);
    // 2) permuted windowed attention -> y (scatter through perm)
    attn2_kernel<<<dim3(TT / QB, HH), 256, ATTN_SMEM_BYTES>>>(qkv, perms, y);
    // 3) out = y @ W_out   (tf32 tensor cores)
    gemm_tf32_kernel<TT, CC, CC><<<dim3(CC / 64, TT / 128), 256>>>(y, Wout, out);
}

// round 3
// speedup vs baseline: 2.0841x; 1.1337x over previous
#include <cuda_runtime.h>
#include <math.h>
#include <stdint.h>

#define TT   2048
#define CC   512
#define HH   8
#define DHD  64
#define WINW 48
#define C3   1536
#define QB   32          // queries per attention block
#define BAND 128         // QB + 2*WIN

// Scratch (device globals — no allocation allowed)
__device__ float g_qkv[TT * C3];   // 12 MB
__device__ float g_y[TT * CC];     // 4 MB

// ---------------------------------------------------------------------------
// TF32 helpers
// ---------------------------------------------------------------------------
__device__ __forceinline__ float to_tf32(float x) {
    float y;
    asm("cvt.rna.tf32.f32 %0, %1;" : "=f"(y) : "f"(x));
    return y;
}

__device__ __forceinline__ void mma_tf32(float& c0, float& c1, float& c2, float& c3,
                                         uint32_t a0, uint32_t a1, uint32_t a2, uint32_t a3,
                                         uint32_t b0, uint32_t b1) {
    asm volatile(
        "mma.sync.aligned.m16n8k8.row.col.f32.tf32.tf32.f32 "
        "{%0,%1,%2,%3}, {%4,%5,%6,%7}, {%8,%9}, {%0,%1,%2,%3};"
        : "+f"(c0), "+f"(c1), "+f"(c2), "+f"(c3)
        : "r"(a0), "r"(a1), "r"(a2), "r"(a3), "r"(b0), "r"(b1));
}

// ---------------------------------------------------------------------------
// TF32 GEMM v3: C[M,N] = A[M,K] @ B[K,N], row-major.
// Block 128x64, 8 warps (4m x 2n), warp 32x32, BK=16, double-buffered smem.
// A staged in (lr, lr+4)-paired float2 layout, stride 12 f2 (conflict-free).
// ---------------------------------------------------------------------------
#define GBM 128
#define GBN 64
#define GBK 16
#define A_K8_STRIDE 1538          // float2 units between the two k8 chunks
#define A_STAGE_F2  (2 * A_K8_STRIDE)              // 3076 float2 per stage
#define B_STAGE_F   (GBK * 68)                     // 1088 floats per stage
#define GEMM_SMEM_BYTES (2 * A_STAGE_F2 * 8 + 2 * B_STAGE_F * 4)   // 57920

template<int M, int N, int K>
__global__ void __launch_bounds__(256, 3) gemm_tf32_kernel(
    const float* __restrict__ A,
    const float* __restrict__ B,
    float* __restrict__ Cout)
{
    extern __shared__ float smemf[];
    float2* As = (float2*)smemf;                       // [2][A_STAGE_F2]
    float*  Bs = smemf + 2 * A_STAGE_F2 * 2;           // [2][B_STAGE_F]

    const int t    = threadIdx.x;
    const int lane = t & 31;
    const int w    = t >> 5;
    const int wm   = (w >> 1) * 32;
    const int wn   = (w & 1) * 32;
    const int m0   = blockIdx.y * GBM;
    const int n0   = blockIdx.x * GBN;
    const int lq   = lane >> 2;
    const int lr   = lane & 3;

    // LDG mapping: A -> row t>>1, k8 chunk t&1 (8 consecutive k)
    const int arow = t >> 1;
    const int ak8  = t & 1;
    const float* Aptr = A + (size_t)(m0 + arow) * K + ak8 * 8;
    // B -> row t>>4 (of 16), col (t&15)*4
    const int brow = t >> 4;
    const int bcol = (t & 15) * 4;
    const float* Bptr = B + (size_t)brow * N + n0 + bcol;

    float  ar[8];
    float4 br;

    float c[2][4][4];
#pragma unroll
    for (int mt = 0; mt < 2; mt++)
#pragma unroll
        for (int nt = 0; nt < 4; nt++)
#pragma unroll
            for (int i = 0; i < 4; i++) c[mt][nt][i] = 0.f;

    // prologue: load step 0, stage 0
    {
        const float4 a0 = *(const float4*)(Aptr);
        const float4 a1 = *(const float4*)(Aptr + 4);
        ar[0]=a0.x; ar[1]=a0.y; ar[2]=a0.z; ar[3]=a0.w;
        ar[4]=a1.x; ar[5]=a1.y; ar[6]=a1.z; ar[7]=a1.w;
        br = *(const float4*)(Bptr);
    }
    {
        float2* dst = &As[ak8 * A_K8_STRIDE + arow * 12];
        float4 v0, v1;
        v0.x = to_tf32(ar[0]); v0.y = to_tf32(ar[4]);
        v0.z = to_tf32(ar[1]); v0.w = to_tf32(ar[5]);
        v1.x = to_tf32(ar[2]); v1.y = to_tf32(ar[6]);
        v1.z = to_tf32(ar[3]); v1.w = to_tf32(ar[7]);
        *(float4*)(dst)     = v0;
        *(float4*)(dst + 2) = v1;
        float4 o;
        o.x = to_tf32(br.x); o.y = to_tf32(br.y);
        o.z = to_tf32(br.z); o.w = to_tf32(br.w);
        *(float4*)&Bs[brow * 68 + bcol] = o;
    }
    __syncthreads();

    int st = 0;
    const int NSTEP = K / GBK;
    for (int s = 0; s < NSTEP; s++) {
        // early-issue next tile's global loads
        if (s + 1 < NSTEP) {
            const float4 a0 = *(const float4*)(Aptr + (s + 1) * GBK);
            const float4 a1 = *(const float4*)(Aptr + (s + 1) * GBK + 4);
            ar[0]=a0.x; ar[1]=a0.y; ar[2]=a0.z; ar[3]=a0.w;
            ar[4]=a1.x; ar[5]=a1.y; ar[6]=a1.z; ar[7]=a1.w;
            br = *(const float4*)(Bptr + (size_t)(s + 1) * GBK * N);
        }

        // compute on stage st
        const float2* AsS = As + st * A_STAGE_F2;
        const float*  BsS = Bs + st * B_STAGE_F;
#pragma unroll
        for (int kk8 = 0; kk8 < 2; kk8++) {
            uint32_t af[2][4];
#pragma unroll
            for (int mt = 0; mt < 2; mt++) {
                const int mb = wm + mt * 16 + lq;
                const float2 p0 = AsS[kk8 * A_K8_STRIDE + mb * 12 + lr];
                const float2 p1 = AsS[kk8 * A_K8_STRIDE + (mb + 8) * 12 + lr];
                af[mt][0] = __float_as_uint(p0.x);
                af[mt][1] = __float_as_uint(p1.x);
                af[mt][2] = __float_as_uint(p0.y);
                af[mt][3] = __float_as_uint(p1.y);
            }
            uint32_t bf[4][2];
#pragma unroll
            for (int nt = 0; nt < 4; nt++) {
                const int col = wn + nt * 8 + lq;
                bf[nt][0] = __float_as_uint(BsS[(kk8 * 8 + lr    ) * 68 + col]);
                bf[nt][1] = __float_as_uint(BsS[(kk8 * 8 + lr + 4) * 68 + col]);
            }
#pragma unroll
            for (int mt = 0; mt < 2; mt++)
#pragma unroll
                for (int nt = 0; nt < 4; nt++)
                    mma_tf32(c[mt][nt][0], c[mt][nt][1], c[mt][nt][2], c[mt][nt][3],
                             af[mt][0], af[mt][1], af[mt][2], af[mt][3],
                             bf[nt][0], bf[nt][1]);
        }

        // stage next tile
        if (s + 1 < NSTEP) {
            float2* dst = &As[(st ^ 1) * A_STAGE_F2 + ak8 * A_K8_STRIDE + arow * 12];
            float4 v0, v1;
            v0.x = to_tf32(ar[0]); v0.y = to_tf32(ar[4]);
            v0.z = to_tf32(ar[1]); v0.w = to_tf32(ar[5]);
            v1.x = to_tf32(ar[2]); v1.y = to_tf32(ar[6]);
            v1.z = to_tf32(ar[3]); v1.w = to_tf32(ar[7]);
            *(float4*)(dst)     = v0;
            *(float4*)(dst + 2) = v1;
            float4 o;
            o.x = to_tf32(br.x); o.y = to_tf32(br.y);
            o.z = to_tf32(br.z); o.w = to_tf32(br.w);
            *(float4*)&Bs[(st ^ 1) * B_STAGE_F + brow * 68 + bcol] = o;
        }
        __syncthreads();
        st ^= 1;
    }

    // epilogue
#pragma unroll
    for (int mt = 0; mt < 2; mt++) {
#pragma unroll
        for (int nt = 0; nt < 4; nt++) {
            const int row0 = m0 + wm + mt * 16 + lq;
            const int col  = n0 + wn + nt * 8 + 2 * lr;
            *(float2*)&Cout[(size_t)row0 * N + col] =
                make_float2(c[mt][nt][0], c[mt][nt][1]);
            *(float2*)&Cout[(size_t)(row0 + 8) * N + col] =
                make_float2(c[mt][nt][2], c[mt][nt][3]);
        }
    }
}

// ---------------------------------------------------------------------------
// Attention (unchanged from R2): block = (head, 32 consecutive permuted
// queries); dense band S = QK^T, masked softmax, Y = WV.
// ---------------------------------------------------------------------------
#define QS_STRIDE  36
#define KS_STRIDE  132
#define VS_STRIDE  68
#define WT_STRIDE  33

#define QS_OFF   0
#define KS_OFF   (QS_OFF + 64 * QS_STRIDE)
#define VS_OFF   (KS_OFF + 64 * KS_STRIDE)
#define WT_OFF   (VS_OFF + BAND * VS_STRIDE)
#define NB_OFF   (WT_OFF + BAND * WT_STRIDE)
#define PT_OFF   (NB_OFF + BAND)
#define ATTN_SMEM_FLOATS (PT_OFF + QB)
#define ATTN_SMEM_BYTES  (ATTN_SMEM_FLOATS * 4)

__global__ void __launch_bounds__(256) attn2_kernel(
    const float* __restrict__ qkv,
    const int* __restrict__ perms,
    float* __restrict__ y)
{
    extern __shared__ float sm[];
    float* Qs = sm + QS_OFF;
    float* Ks = sm + KS_OFF;
    float* Vs = sm + VS_OFF;
    float* Wt = sm + WT_OFF;
    int*   nb = (int*)(sm + NB_OFF);
    int*   pts = (int*)(sm + PT_OFF);

    const int h    = blockIdx.y;
    const int t0   = blockIdx.x * QB;
    const int t    = threadIdx.x;
    const int lane = t & 31;
    const int w    = t >> 5;

    const int* __restrict__ perm = perms + h * TT;

    for (int i = t; i < BAND + QB; i += 256) {
        if (i < BAND) {
            int j  = t0 - WINW + i;
            int jc = min(max(j, 0), TT - 1);
            nb[i] = perm[jc];
        } else {
            pts[i - BAND] = perm[t0 + (i - BAND)];
        }
    }
    __syncthreads();

    for (int it = 0; it < BAND / 8; it++) {
        const int r = it * 8 + w;
        const float2 kv = *(const float2*)&qkv[(size_t)nb[r] * C3 + CC + h * DHD + 2 * lane];
        Ks[(2 * lane    ) * KS_STRIDE + r] = kv.x;
        Ks[(2 * lane + 1) * KS_STRIDE + r] = kv.y;
        const float2 vv = *(const float2*)&qkv[(size_t)nb[r] * C3 + 2 * CC + h * DHD + 2 * lane];
        *(float2*)&Vs[r * VS_STRIDE + 2 * lane] = vv;
    }
    for (int it = 0; it < QB / 8; it++) {
        const int q = it * 8 + w;
        const float2 qv = *(const float2*)&qkv[(size_t)pts[q] * C3 + h * DHD + 2 * lane];
        Qs[(2 * lane    ) * QS_STRIDE + q] = qv.x * 0.125f;
        Qs[(2 * lane + 1) * QS_STRIDE + q] = qv.y * 0.125f;
    }
    __syncthreads();

    {
        const int tq = t >> 5;
        const int tr = t & 31;
        float acc[4][4];
#pragma unroll
        for (int i = 0; i < 4; i++)
#pragma unroll
            for (int j = 0; j < 4; j++) acc[i][j] = 0.f;

#pragma unroll 4
        for (int d = 0; d < DHD; d++) {
            const float4 qv = *(const float4*)&Qs[d * QS_STRIDE + tq * 4];
            const float4 kv = *(const float4*)&Ks[d * KS_STRIDE + tr * 4];
            const float qa[4] = {qv.x, qv.y, qv.z, qv.w};
            const float ka[4] = {kv.x, kv.y, kv.z, kv.w};
#pragma unroll
            for (int i = 0; i < 4; i++)
#pragma unroll
                for (int j = 0; j < 4; j++)
                    acc[i][j] = fmaf(qa[i], ka[j], acc[i][j]);
        }
#pragma unroll
        for (int i = 0; i < 4; i++)
#pragma unroll
            for (int j = 0; j < 4; j++)
                Wt[(tr * 4 + j) * WT_STRIDE + tq * 4 + i] = acc[i][j];
    }
    __syncthreads();

    for (int qq = w; qq < QB; qq += 8) {
        const int pt = pts[qq];
        float v[4];
#pragma unroll
        for (int c = 0; c < 4; c++) {
            const int r = lane + 32 * c;
            const bool m = (r >= qq) && (r <= qq + 96) &&
                           ((unsigned)(t0 - WINW + r) < (unsigned)TT) &&
                           (nb[r] <= pt);
            v[c] = m ? Wt[r * WT_STRIDE + qq] : -INFINITY;
        }
        float mx = fmaxf(fmaxf(v[0], v[1]), fmaxf(v[2], v[3]));
#pragma unroll
        for (int off = 16; off; off >>= 1)
            mx = fmaxf(mx, __shfl_xor_sync(0xffffffffu, mx, off));
        float e[4], s = 0.f;
#pragma unroll
        for (int c = 0; c < 4; c++) { e[c] = __expf(v[c] - mx); s += e[c]; }
#pragma unroll
        for (int off = 16; off; off >>= 1)
            s += __shfl_xor_sync(0xffffffffu, s, off);
        const float inv = 1.f / s;
#pragma unroll
        for (int c = 0; c < 4; c++) {
            const int r = lane + 32 * c;
            Wt[r * WT_STRIDE + qq] = e[c] * inv;
        }
    }
    __syncthreads();

    {
        const int tq = t >> 5;
        const int td = t & 31;
        float a0[4], a1[4];
#pragma unroll
        for (int i = 0; i < 4; i++) { a0[i] = 0.f; a1[i] = 0.f; }

#pragma unroll 4
        for (int r = 0; r < BAND; r++) {
            const float2 vv = *(const float2*)&Vs[r * VS_STRIDE + td * 2];
            const float* wr = &Wt[r * WT_STRIDE + tq * 4];
#pragma unroll
            for (int i = 0; i < 4; i++) {
                const float wi = wr[i];
                a0[i] = fmaf(wi, vv.x, a0[i]);
                a1[i] = fmaf(wi, vv.y, a1[i]);
            }
        }
#pragma unroll
        for (int i = 0; i < 4; i++) {
            const int q  = tq * 4 + i;
            const int pt = pts[q];
            *(float2*)&y[(size_t)pt * CC + h * DHD + td * 2] = make_float2(a0[i], a1[i]);
        }
    }
}

// ---------------------------------------------------------------------------
extern "C" void kernel_launch(void* const* d_in, const int* in_sizes, int n_in,
                              void* d_out, int out_size) {
    (void)in_sizes; (void)n_in; (void)out_size;
    const float* x     = (const float*)d_in[0];
    const float* Wqkv  = (const float*)d_in[1];
    const float* Wout  = (const float*)d_in[2];
    const int*   perms = (const int*)d_in[3];
    float*       out   = (float*)d_out;

    float* qkv = nullptr;
    float* y   = nullptr;
    cudaGetSymbolAddress((void**)&qkv, g_qkv);
    cudaGetSymbolAddress((void**)&y,   g_y);

    cudaFuncSetAttribute(gemm_tf32_kernel<TT, C3, CC>,
                         cudaFuncAttributeMaxDynamicSharedMemorySize, GEMM_SMEM_BYTES);
    cudaFuncSetAttribute(gemm_tf32_kernel<TT, CC, CC>,
                         cudaFuncAttributeMaxDynamicSharedMemorySize, GEMM_SMEM_BYTES);
    cudaFuncSetAttribute(attn2_kernel,
                         cudaFuncAttributeMaxDynamicSharedMemorySize, ATTN_SMEM_BYTES);

    gemm_tf32_kernel<TT, C3, CC><<<dim3(C3 / GBN, TT / GBM), 256, GEMM_SMEM_BYTES>>>(x, Wqkv, qkv);
    attn2_kernel<<<dim3(TT / QB, HH), 256, ATTN_SMEM_BYTES>>>(qkv, perms, y);
    gemm_tf32_kernel<TT, CC, CC><<<dim3(CC / GBN, TT / GBM), 256, GEMM_SMEM_BYTES>>>(y, Wout, out);
}

// round 4
// speedup vs baseline: 2.4618x; 1.1813x over previous
#include <cuda_runtime.h>
#include <math.h>
#include <stdint.h>

#define TT   2048
#define CC   512
#define HH   8
#define DHD  64
#define WINW 48
#define C3   1536
#define QB   32
#define BAND 128

// Scratch (device globals — no allocation allowed)
__device__ float g_qkv[TT * C3];        // 12 MB
__device__ float g_y[TT * CC];          // 4 MB
__device__ float g_x32[TT * CC];        // tf32-rounded x
__device__ float g_wqkv32[CC * C3];     // tf32-rounded W_qkv
__device__ float g_wout32[CC * CC];     // tf32-rounded W_out

// ---------------------------------------------------------------------------
__device__ __forceinline__ float to_tf32(float x) {
    float y;
    asm("cvt.rna.tf32.f32 %0, %1;" : "=f"(y) : "f"(x));
    return y;
}

__device__ __forceinline__ void mma_tf32(float& c0, float& c1, float& c2, float& c3,
                                         uint32_t a0, uint32_t a1, uint32_t a2, uint32_t a3,
                                         uint32_t b0, uint32_t b1) {
    asm volatile(
        "mma.sync.aligned.m16n8k8.row.col.f32.tf32.tf32.f32 "
        "{%0,%1,%2,%3}, {%4,%5,%6,%7}, {%8,%9}, {%0,%1,%2,%3};"
        : "+f"(c0), "+f"(c1), "+f"(c2), "+f"(c3)
        : "r"(a0), "r"(a1), "r"(a2), "r"(a3), "r"(b0), "r"(b1));
}

#define CP_ASYNC16(dst, src) \
    asm volatile("cp.async.cg.shared.global [%0], [%1], 16;\n" :: "r"(dst), "l"(src))
#define CP_COMMIT() asm volatile("cp.async.commit_group;\n" ::)
#define CP_WAIT2()  asm volatile("cp.async.wait_group 2;\n" ::)

// ---------------------------------------------------------------------------
// Prep: round x, W_qkv, W_out to tf32 precision (rna) into scratch copies.
// Flat float4 grid over the three concatenated arrays.
// ---------------------------------------------------------------------------
#define XF4   (TT * CC / 4)          // 262144
#define WQF4  (CC * C3 / 4)          // 196608
#define WOF4  (CC * CC / 4)          // 65536
#define PREPF4 (XF4 + WQF4 + WOF4)   // 524288

__global__ void prep_tf32_kernel(const float4* __restrict__ x,
                                 const float4* __restrict__ wq,
                                 const float4* __restrict__ wo,
                                 float4* __restrict__ xo,
                                 float4* __restrict__ wqo,
                                 float4* __restrict__ woo) {
    int i = blockIdx.x * blockDim.x + threadIdx.x;
    if (i >= PREPF4) return;
    const float4* src;
    float4* dst;
    int j = i;
    if (j < XF4) { src = x; dst = xo; }
    else if (j < XF4 + WQF4) { j -= XF4; src = wq; dst = wqo; }
    else { j -= XF4 + WQF4; src = wo; dst = woo; }
    float4 v = src[j];
    v.x = to_tf32(v.x); v.y = to_tf32(v.y);
    v.z = to_tf32(v.z); v.w = to_tf32(v.w);
    dst[j] = v;
}

// ---------------------------------------------------------------------------
// TF32 GEMM v4: cp.async 4-stage pipeline.
// C[M,N] = A[M,K] @ B[K,N], row-major, inputs pre-rounded to tf32.
// Block 128x64, 8 warps (4m x 2n), warp 32x32, BK=16.
// A smem: [stage][128][20] (stride-20 floats, conflict-free frag loads)
// B smem: [stage][16][72]  (stride-72, conflict-free frag loads)
// ---------------------------------------------------------------------------
#define GBM 128
#define GBN 64
#define GBK 16
#define NSTAGE 4
#define A_ST (128 * 20)              // floats per A stage = 2560
#define B_ST (16 * 72)               // floats per B stage = 1152
#define GEMM_SMEM_BYTES ((NSTAGE * A_ST + NSTAGE * B_ST) * 4)   // 59392

template<int M, int N, int K>
__global__ void __launch_bounds__(256, 3) gemm_tf32_kernel(
    const float* __restrict__ A,
    const float* __restrict__ B,
    float* __restrict__ Cout)
{
    extern __shared__ float smemf[];
    float* As = smemf;
    float* Bs = smemf + NSTAGE * A_ST;

    const int t    = threadIdx.x;
    const int lane = t & 31;
    const int w    = t >> 5;
    const int wm   = (w >> 1) * 32;
    const int wn   = (w & 1) * 32;
    const int m0   = blockIdx.y * GBM;
    const int n0   = blockIdx.x * GBN;
    const int lq   = lane >> 2;
    const int lr   = lane & 3;

    // cp.async source/dest mapping
    const int arow = t >> 1;            // 0..127
    const int ak8  = t & 1;             // which 8-float chunk pair
    const int brow = t >> 4;            // 0..15
    const int bcol = (t & 15) * 4;

    const float* Abase = A + (size_t)(m0 + arow) * K + ak8 * 8;
    const float* Bbase = B + (size_t)brow * N + n0 + bcol;

    uint32_t as_base = (uint32_t)__cvta_generic_to_shared(As) +
                       (arow * 20 + ak8 * 8) * 4;
    uint32_t bs_base = (uint32_t)__cvta_generic_to_shared(Bs) +
                       (brow * 72 + bcol) * 4;

    float c[2][4][4];
#pragma unroll
    for (int mt = 0; mt < 2; mt++)
#pragma unroll
        for (int nt = 0; nt < 4; nt++)
#pragma unroll
            for (int i = 0; i < 4; i++) c[mt][nt][i] = 0.f;

    const int NSTEP = K / GBK;

    // prologue: stages 0..2
#pragma unroll
    for (int p = 0; p < NSTAGE - 1; p++) {
        const float* asrc = Abase + p * GBK;
        uint32_t adst = as_base + p * A_ST * 4;
        CP_ASYNC16(adst, asrc);
        CP_ASYNC16(adst + 16, asrc + 4);
        const float* bsrc = Bbase + (size_t)p * GBK * N;
        CP_ASYNC16(bs_base + p * B_ST * 4, bsrc);
        CP_COMMIT();
    }

    for (int s = 0; s < NSTEP; s++) {
        CP_WAIT2();
        __syncthreads();

        // issue copy for step s+3 into stage (s+3)%4 (== (s-1)%4, freed by barrier)
        if (s + NSTAGE - 1 < NSTEP) {
            const int stg = (s + NSTAGE - 1) & (NSTAGE - 1);
            const float* asrc = Abase + (s + NSTAGE - 1) * GBK;
            uint32_t adst = as_base + stg * A_ST * 4;
            CP_ASYNC16(adst, asrc);
            CP_ASYNC16(adst + 16, asrc + 4);
            const float* bsrc = Bbase + (size_t)(s + NSTAGE - 1) * GBK * N;
            CP_ASYNC16(bs_base + stg * B_ST * 4, bsrc);
        }
        CP_COMMIT();

        const float* AsS = As + (s & (NSTAGE - 1)) * A_ST;
        const float* BsS = Bs + (s & (NSTAGE - 1)) * B_ST;

#pragma unroll
        for (int kk8 = 0; kk8 < 2; kk8++) {
            const int kb = kk8 * 8;
            uint32_t af[2][4];
#pragma unroll
            for (int mt = 0; mt < 2; mt++) {
                const int r0 = (wm + mt * 16 + lq) * 20;
                af[mt][0] = __float_as_uint(AsS[r0 + kb + lr]);
                af[mt][1] = __float_as_uint(AsS[r0 + 160 + kb + lr]);       // +8 rows
                af[mt][2] = __float_as_uint(AsS[r0 + kb + lr + 4]);
                af[mt][3] = __float_as_uint(AsS[r0 + 160 + kb + lr + 4]);
            }
            uint32_t bf[4][2];
#pragma unroll
            for (int nt = 0; nt < 4; nt++) {
                const int col = wn + nt * 8 + lq;
                bf[nt][0] = __float_as_uint(BsS[(kb + lr) * 72 + col]);
                bf[nt][1] = __float_as_uint(BsS[(kb + lr + 4) * 72 + col]);
            }
#pragma unroll
            for (int mt = 0; mt < 2; mt++)
#pragma unroll
                for (int nt = 0; nt < 4; nt++)
                    mma_tf32(c[mt][nt][0], c[mt][nt][1], c[mt][nt][2], c[mt][nt][3],
                             af[mt][0], af[mt][1], af[mt][2], af[mt][3],
                             bf[nt][0], bf[nt][1]);
        }
    }

    // epilogue
#pragma unroll
    for (int mt = 0; mt < 2; mt++) {
#pragma unroll
        for (int nt = 0; nt < 4; nt++) {
            const int row0 = m0 + wm + mt * 16 + lq;
            const int col  = n0 + wn + nt * 8 + 2 * lr;
            *(float2*)&Cout[(size_t)row0 * N + col] =
                make_float2(c[mt][nt][0], c[mt][nt][1]);
            *(float2*)&Cout[(size_t)(row0 + 8) * N + col] =
                make_float2(c[mt][nt][2], c[mt][nt][3]);
        }
    }
}

// ---------------------------------------------------------------------------
// Attention (R2/R3 design, unchanged except tf32-rounding of the y output
// so gemm2 can consume it raw).
// ---------------------------------------------------------------------------
#define QS_STRIDE  36
#define KS_STRIDE  132
#define VS_STRIDE  68
#define WT_STRIDE  33

#define QS_OFF   0
#define KS_OFF   (QS_OFF + 64 * QS_STRIDE)
#define VS_OFF   (KS_OFF + 64 * KS_STRIDE)
#define WT_OFF   (VS_OFF + BAND * VS_STRIDE)
#define NB_OFF   (WT_OFF + BAND * WT_STRIDE)
#define PT_OFF   (NB_OFF + BAND)
#define ATTN_SMEM_FLOATS (PT_OFF + QB)
#define ATTN_SMEM_BYTES  (ATTN_SMEM_FLOATS * 4)

__global__ void __launch_bounds__(256) attn2_kernel(
    const float* __restrict__ qkv,
    const int* __restrict__ perms,
    float* __restrict__ y)
{
    extern __shared__ float sm[];
    float* Qs = sm + QS_OFF;
    float* Ks = sm + KS_OFF;
    float* Vs = sm + VS_OFF;
    float* Wt = sm + WT_OFF;
    int*   nb = (int*)(sm + NB_OFF);
    int*   pts = (int*)(sm + PT_OFF);

    const int h    = blockIdx.y;
    const int t0   = blockIdx.x * QB;
    const int t    = threadIdx.x;
    const int lane = t & 31;
    const int w    = t >> 5;

    const int* __restrict__ perm = perms + h * TT;

    for (int i = t; i < BAND + QB; i += 256) {
        if (i < BAND) {
            int j  = t0 - WINW + i;
            int jc = min(max(j, 0), TT - 1);
            nb[i] = perm[jc];
        } else {
            pts[i - BAND] = perm[t0 + (i - BAND)];
        }
    }
    __syncthreads();

    for (int it = 0; it < BAND / 8; it++) {
        const int r = it * 8 + w;
        const float2 kv = *(const float2*)&qkv[(size_t)nb[r] * C3 + CC + h * DHD + 2 * lane];
        Ks[(2 * lane    ) * KS_STRIDE + r] = kv.x;
        Ks[(2 * lane + 1) * KS_STRIDE + r] = kv.y;
        const float2 vv = *(const float2*)&qkv[(size_t)nb[r] * C3 + 2 * CC + h * DHD + 2 * lane];
        *(float2*)&Vs[r * VS_STRIDE + 2 * lane] = vv;
    }
    for (int it = 0; it < QB / 8; it++) {
        const int q = it * 8 + w;
        const float2 qv = *(const float2*)&qkv[(size_t)pts[q] * C3 + h * DHD + 2 * lane];
        Qs[(2 * lane    ) * QS_STRIDE + q] = qv.x * 0.125f;
        Qs[(2 * lane + 1) * QS_STRIDE + q] = qv.y * 0.125f;
    }
    __syncthreads();

    {
        const int tq = t >> 5;
        const int tr = t & 31;
        float acc[4][4];
#pragma unroll
        for (int i = 0; i < 4; i++)
#pragma unroll
            for (int j = 0; j < 4; j++) acc[i][j] = 0.f;

#pragma unroll 4
        for (int d = 0; d < DHD; d++) {
            const float4 qv = *(const float4*)&Qs[d * QS_STRIDE + tq * 4];
            const float4 kv = *(const float4*)&Ks[d * KS_STRIDE + tr * 4];
            const float qa[4] = {qv.x, qv.y, qv.z, qv.w};
            const float ka[4] = {kv.x, kv.y, kv.z, kv.w};
#pragma unroll
            for (int i = 0; i < 4; i++)
#pragma unroll
                for (int j = 0; j < 4; j++)
                    acc[i][j] = fmaf(qa[i], ka[j], acc[i][j]);
        }
#pragma unroll
        for (int i = 0; i < 4; i++)
#pragma unroll
            for (int j = 0; j < 4; j++)
                Wt[(tr * 4 + j) * WT_STRIDE + tq * 4 + i] = acc[i][j];
    }
    __syncthreads();

    for (int qq = w; qq < QB; qq += 8) {
        const int pt = pts[qq];
        float v[4];
#pragma unroll
        for (int c = 0; c < 4; c++) {
            const int r = lane + 32 * c;
            const bool m = (r >= qq) && (r <= qq + 96) &&
                           ((unsigned)(t0 - WINW + r) < (unsigned)TT) &&
                           (nb[r] <= pt);
            v[c] = m ? Wt[r * WT_STRIDE + qq] : -INFINITY;
        }
        float mx = fmaxf(fmaxf(v[0], v[1]), fmaxf(v[2], v[3]));
#pragma unroll
        for (int off = 16; off; off >>= 1)
            mx = fmaxf(mx, __shfl_xor_sync(0xffffffffu, mx, off));
        float e[4], s = 0.f;
#pragma unroll
        for (int c = 0; c < 4; c++) { e[c] = __expf(v[c] - mx); s += e[c]; }
#pragma unroll
        for (int off = 16; off; off >>= 1)
            s += __shfl_xor_sync(0xffffffffu, s, off);
        const float inv = 1.f / s;
#pragma unroll
        for (int c = 0; c < 4; c++) {
            const int r = lane + 32 * c;
            Wt[r * WT_STRIDE + qq] = e[c] * inv;
        }
    }
    __syncthreads();

    {
        const int tq = t >> 5;
        const int td = t & 31;
        float a0[4], a1[4];
#pragma unroll
        for (int i = 0; i < 4; i++) { a0[i] = 0.f; a1[i] = 0.f; }

#pragma unroll 4
        for (int r = 0; r < BAND; r++) {
            const float2 vv = *(const float2*)&Vs[r * VS_STRIDE + td * 2];
            const float* wr = &Wt[r * WT_STRIDE + tq * 4];
#pragma unroll
            for (int i = 0; i < 4; i++) {
                const float wi = wr[i];
                a0[i] = fmaf(wi, vv.x, a0[i]);
                a1[i] = fmaf(wi, vv.y, a1[i]);
            }
        }
#pragma unroll
        for (int i = 0; i < 4; i++) {
            const int q  = tq * 4 + i;
            const int pt = pts[q];
            // tf32-round y so gemm2 consumes pre-rounded data
            *(float2*)&y[(size_t)pt * CC + h * DHD + td * 2] =
                make_float2(to_tf32(a0[i]), to_tf32(a1[i]));
        }
    }
}

// ---------------------------------------------------------------------------
extern "C" void kernel_launch(void* const* d_in, const int* in_sizes, int n_in,
                              void* d_out, int out_size) {
    (void)in_sizes; (void)n_in; (void)out_size;
    const float* x     = (const float*)d_in[0];
    const float* Wqkv  = (const float*)d_in[1];
    const float* Wout  = (const float*)d_in[2];
    const int*   perms = (const int*)d_in[3];
    float*       out   = (float*)d_out;

    float *qkv, *y, *x32, *wq32, *wo32;
    cudaGetSymbolAddress((void**)&qkv,  g_qkv);
    cudaGetSymbolAddress((void**)&y,    g_y);
    cudaGetSymbolAddress((void**)&x32,  g_x32);
    cudaGetSymbolAddress((void**)&wq32, g_wqkv32);
    cudaGetSymbolAddress((void**)&wo32, g_wout32);

    cudaFuncSetAttribute(gemm_tf32_kernel<TT, C3, CC>,
                         cudaFuncAttributeMaxDynamicSharedMemorySize, GEMM_SMEM_BYTES);
    cudaFuncSetAttribute(gemm_tf32_kernel<TT, CC, CC>,
                         cudaFuncAttributeMaxDynamicSharedMemorySize, GEMM_SMEM_BYTES);
    cudaFuncSetAttribute(attn2_kernel,
                         cudaFuncAttributeMaxDynamicSharedMemorySize, ATTN_SMEM_BYTES);

    // 0) round inputs to tf32 (rna)
    prep_tf32_kernel<<<PREPF4 / 256, 256>>>(
        (const float4*)x, (const float4*)Wqkv, (const float4*)Wout,
        (float4*)x32, (float4*)wq32, (float4*)wo32);
    // 1) qkv = x @ W_qkv
    gemm_tf32_kernel<TT, C3, CC><<<dim3(C3 / GBN, TT / GBM), 256, GEMM_SMEM_BYTES>>>(x32, wq32, qkv);
    // 2) attention
    attn2_kernel<<<dim3(TT / QB, HH), 256, ATTN_SMEM_BYTES>>>(qkv, perms, y);
    // 3) out = y @ W_out
    gemm_tf32_kernel<TT, CC, CC><<<dim3(CC / GBN, TT / GBM), 256, GEMM_SMEM_BYTES>>>(y, wo32, out);
}